// round 1
// baseline (speedup 1.0000x reference)
#include <cuda_runtime.h>

// Problem constants
#define Bb   128
#define Tt   256
#define Nn   16
#define Kk   10
#define Hh   20
#define BT   32768          // Bb*Tt
#define KT   (Kk*Tt)        // 2560

// Scratch (static device globals — no allocation)
__device__ float g_xs[Nn * BT];                    // standardized x, [n][b*T+t], 2 MB
__device__ float g_t [(size_t)Kk * BT * Nn];       // t values, [k][j][n], 20 MB
__device__ float g_sq[KT];                         // per-(k,t) squared diffs

// ---------------------------------------------------------------------------
// Kernel 1: standardize x over batch dim (per (t,n) column, ddof=1), write
// transposed into g_xs[n][b*T+t] so stage 2 reads are fully coalesced.
// One warp per column. 4096 columns.
// ---------------------------------------------------------------------------
__global__ void __launch_bounds__(256) standardize_x_kernel(const float* __restrict__ x) {
    int col  = blockIdx.x * 8 + (threadIdx.x >> 5);   // 0..4095
    int lane = threadIdx.x & 31;
    int tt = col >> 4;      // col / N
    int n  = col & 15;      // col % N

    float v[4];
    float s = 0.f;
#pragma unroll
    for (int q = 0; q < 4; q++) {
        int b = lane + q * 32;
        v[q] = x[(b * Tt + tt) * Nn + n];
        s += v[q];
    }
#pragma unroll
    for (int o = 16; o; o >>= 1) s += __shfl_xor_sync(0xffffffffu, s, o);
    float mu = s * (1.f / 128.f);

    float ss = 0.f;
#pragma unroll
    for (int q = 0; q < 4; q++) { float d = v[q] - mu; ss += d * d; }
#pragma unroll
    for (int o = 16; o; o >>= 1) ss += __shfl_xor_sync(0xffffffffu, ss, o);

    float inv = 1.f / sqrtf(ss * (1.f / 127.f));      // unbiased std, no eps
#pragma unroll
    for (int q = 0; q < 4; q++) {
        int b = lane + q * 32;
        g_xs[n * BT + b * Tt + tt] = (v[q] - mu) * inv;
    }
}

// ---------------------------------------------------------------------------
// Kernel 2: the MLP sweep. One block handles one (k,n) pair for a chunk of
// j = b*T+t indices; weights live in shared memory (broadcast LDS).
// grid = (K*N, CHUNKS), block = 256, CHUNKS*256*ITERS = BT.
// ---------------------------------------------------------------------------
#define CHUNKS 16
#define ITERS  (BT / CHUNKS / 256)   // 8

__global__ void __launch_bounds__(256) mlp_kernel(
    const float* __restrict__ W1, const float* __restrict__ b1,
    const float* __restrict__ W2, const float* __restrict__ b2,
    const float* __restrict__ W3, const float* __restrict__ b3)
{
    __shared__ float sw2[Hh * Hh];
    __shared__ float sw1[Hh], sb1[Hh], sb2[Hh], sw3[Hh];
    __shared__ float sb3;

    int kn = blockIdx.x;          // k*N + n, 0..159
    int n  = kn & 15;
    int k  = kn >> 4;

    for (int i = threadIdx.x; i < Hh * Hh; i += 256) sw2[i] = W2[kn * Hh * Hh + i];
    if (threadIdx.x < Hh) {
        sw1[threadIdx.x] = W1[kn * Hh + threadIdx.x];
        sb1[threadIdx.x] = b1[kn * Hh + threadIdx.x];
        sb2[threadIdx.x] = b2[kn * Hh + threadIdx.x];
        sw3[threadIdx.x] = W3[kn * Hh + threadIdx.x];
    }
    if (threadIdx.x == 0) sb3 = b3[kn];
    __syncthreads();

    const float* xs = g_xs + n * BT;
    float* tout = g_t + (size_t)k * BT * Nn + n;

    int j = blockIdx.y * (BT / CHUNKS) + threadIdx.x;
#pragma unroll 1
    for (int it = 0; it < ITERS; ++it, j += 256) {
        float x = xs[j];

        float h[Hh];
#pragma unroll
        for (int i = 0; i < Hh; i++) h[i] = fmaxf(fmaf(x, sw1[i], sb1[i]), 0.f);

        // LayerNorm 1 (biased var, eps=1e-5)
        float mu = 0.f;
#pragma unroll
        for (int i = 0; i < Hh; i++) mu += h[i];
        mu *= (1.f / Hh);
        float var = 0.f;
#pragma unroll
        for (int i = 0; i < Hh; i++) { float d = h[i] - mu; var += d * d; }
        var *= (1.f / Hh);
        float r = rsqrtf(var + 1e-5f);
#pragma unroll
        for (int i = 0; i < Hh; i++) h[i] = (h[i] - mu) * r;

        // 20x20 matmul + bias + relu
        float h2[Hh];
#pragma unroll
        for (int o = 0; o < Hh; o++) {
            const float4* w = (const float4*)(sw2 + o * Hh);   // 80B-aligned rows
            float a = sb2[o];
#pragma unroll
            for (int q = 0; q < Hh / 4; q++) {
                float4 wv = w[q];
                a = fmaf(h[q * 4 + 0], wv.x, a);
                a = fmaf(h[q * 4 + 1], wv.y, a);
                a = fmaf(h[q * 4 + 2], wv.z, a);
                a = fmaf(h[q * 4 + 3], wv.w, a);
            }
            h2[o] = fmaxf(a, 0.f);
        }

        // LayerNorm 2
        mu = 0.f;
#pragma unroll
        for (int i = 0; i < Hh; i++) mu += h2[i];
        mu *= (1.f / Hh);
        var = 0.f;
#pragma unroll
        for (int i = 0; i < Hh; i++) { float d = h2[i] - mu; var += d * d; }
        var *= (1.f / Hh);
        r = rsqrtf(var + 1e-5f);

        // output head (fold LN into the dot: (h2-mu)*r dot w3 + b3)
        float out = sb3;
#pragma unroll
        for (int i = 0; i < Hh; i++) out = fmaf((h2[i] - mu) * r, sw3[i], out);

        tout[(size_t)j * Nn] = out;
    }
}

// ---------------------------------------------------------------------------
// Kernel 3: per (k,t): load the 128x16 tile, standardize over b (ddof=1,
// eps=1e-8 added to std), compute prod-of-marginals and prod_joint mean,
// write squared diff.
// grid = K*T = 2560 blocks, 128 threads.
// ---------------------------------------------------------------------------
__global__ void __launch_bounds__(128) penalty_kernel() {
    int kt = blockIdx.x;
    int k  = kt >> 8;     // / T
    int tt = kt & 255;

    __shared__ float s[128 * 17];    // padded tile
    __shared__ float red[128];
    __shared__ float smu[16], srstd[16], spm[16];

    int tid = threadIdx.x;           // = b for row ops

    // load row b=tid: 16 contiguous floats (64B)
    const float4* src = (const float4*)(g_t + ((size_t)k * BT + tid * Tt + tt) * Nn);
#pragma unroll
    for (int q = 0; q < 4; q++) {
        float4 v = src[q];
        s[tid * 17 + q * 4 + 0] = v.x;
        s[tid * 17 + q * 4 + 1] = v.y;
        s[tid * 17 + q * 4 + 2] = v.z;
        s[tid * 17 + q * 4 + 3] = v.w;
    }
    __syncthreads();

    int n = tid & 15, g = tid >> 4;   // 8 groups x 16 n

    // pass 1: mean over b per n
    float p = 0.f;
#pragma unroll
    for (int bb = 0; bb < 16; bb++) p += s[(g * 16 + bb) * 17 + n];
    red[tid] = p;
    __syncthreads();
    if (tid < 16) {
        float m = 0.f;
#pragma unroll
        for (int gg = 0; gg < 8; gg++) m += red[gg * 16 + tid];
        smu[tid] = m * (1.f / 128.f);
    }
    __syncthreads();

    // pass 2: var over b per n (ddof=1), rstd = 1/(std + 1e-8)
    float mun = smu[n];
    float q2 = 0.f;
#pragma unroll
    for (int bb = 0; bb < 16; bb++) {
        float d = s[(g * 16 + bb) * 17 + n] - mun;
        q2 += d * d;
    }
    red[tid] = q2;
    __syncthreads();
    if (tid < 16) {
        float ssum = 0.f;
#pragma unroll
        for (int gg = 0; gg < 8; gg++) ssum += red[gg * 16 + tid];
        srstd[tid] = 1.f / (sqrtf(ssum * (1.f / 127.f)) + 1e-8f);
    }
    __syncthreads();

    // marginal means of standardized values (≈0, matches reference rounding)
    float rn = srstd[n];
    float ps = 0.f;
#pragma unroll
    for (int bb = 0; bb < 16; bb++)
        ps += (s[(g * 16 + bb) * 17 + n] - mun) * rn;
    red[tid] = ps;
    __syncthreads();
    if (tid < 16) {
        float m = 0.f;
#pragma unroll
        for (int gg = 0; gg < 8; gg++) m += red[gg * 16 + tid];
        spm[tid] = m * (1.f / 128.f);
    }
    __syncthreads();

    // prod over n per b, then mean over b
    float prod = 1.f;
#pragma unroll
    for (int nn = 0; nn < 16; nn++)
        prod *= (s[tid * 17 + nn] - smu[nn]) * srstd[nn];
    red[tid] = prod;
    __syncthreads();
#pragma unroll
    for (int off = 64; off; off >>= 1) {
        if (tid < off) red[tid] += red[tid + off];
        __syncthreads();
    }

    if (tid == 0) {
        float pj = red[0] * (1.f / 128.f);
        float pm = 1.f;
#pragma unroll
        for (int nn = 0; nn < 16; nn++) pm *= spm[nn];
        float d = pm - pj;
        g_sq[kt] = d * d;
    }
}

// ---------------------------------------------------------------------------
// Kernel 4: deterministic final reduction to the scalar.
// ---------------------------------------------------------------------------
__global__ void __launch_bounds__(256) reduce_kernel(float* __restrict__ out) {
    __shared__ float red[256];
    float sum = 0.f;
    for (int i = threadIdx.x; i < KT; i += 256) sum += g_sq[i];
    red[threadIdx.x] = sum;
    __syncthreads();
#pragma unroll
    for (int off = 128; off; off >>= 1) {
        if (threadIdx.x < off) red[threadIdx.x] += red[threadIdx.x + off];
        __syncthreads();
    }
    if (threadIdx.x == 0) out[0] = red[0] * (1.f / (float)KT);
}

// ---------------------------------------------------------------------------
extern "C" void kernel_launch(void* const* d_in, const int* in_sizes, int n_in,
                              void* d_out, int out_size) {
    const float* x  = (const float*)d_in[0];
    const float* W1 = (const float*)d_in[1];
    const float* b1 = (const float*)d_in[2];
    const float* W2 = (const float*)d_in[3];
    const float* b2 = (const float*)d_in[4];
    const float* W3 = (const float*)d_in[5];
    const float* b3 = (const float*)d_in[6];

    standardize_x_kernel<<<512, 256>>>(x);

    dim3 g2(Kk * Nn, CHUNKS);
    mlp_kernel<<<g2, 256>>>(W1, b1, W2, b2, W3, b3);

    penalty_kernel<<<KT, 128>>>();

    reduce_kernel<<<1, 256>>>((float*)d_out);
}

// round 2
// speedup vs baseline: 4.0856x; 4.0856x over previous
#include <cuda_runtime.h>

// Problem constants
#define Bb   128
#define Tt   256
#define Nn   16
#define Kk   10
#define Hh   20
#define BT   32768          // Bb*Tt
#define KT   (Kk*Tt)        // 2560

typedef unsigned long long u64;

// Scratch (static device globals — no allocation)
__device__ float g_xs[Nn * BT];                    // standardized x, [n][j], 2 MB
__device__ float g_t [(size_t)Kk * Nn * BT];       // t values, [k][n][j], 20 MB
__device__ float g_sq[KT];                         // per-(k,t) squared diffs

// ---------------- packed f32x2 helpers ----------------
__device__ __forceinline__ u64 pk(float lo, float hi) {
    u64 r; asm("mov.b64 %0,{%1,%2};" : "=l"(r) : "f"(lo), "f"(hi)); return r;
}
__device__ __forceinline__ float2 up(u64 v) {
    float2 f; asm("mov.b64 {%0,%1},%2;" : "=f"(f.x), "=f"(f.y) : "l"(v)); return f;
}
#define FMA2(d,a,b,c) asm("fma.rn.f32x2 %0,%1,%2,%3;" : "=l"(d) : "l"(a), "l"(b), "l"(c))
#define ADD2(d,a,b)   asm("add.rn.f32x2 %0,%1,%2;"    : "=l"(d) : "l"(a), "l"(b))
#define MUL2(d,a,b)   asm("mul.rn.f32x2 %0,%1,%2;"    : "=l"(d) : "l"(a), "l"(b))

__device__ __forceinline__ u64 relu2(u64 v) {
    float2 f = up(v);
    return pk(fmaxf(f.x, 0.f), fmaxf(f.y, 0.f));
}

// ---------------------------------------------------------------------------
// Kernel 1: standardize x over batch dim (per (t,n) column, ddof=1), write
// transposed into g_xs[n][b*T+t]. One warp per column, 4096 columns.
// ---------------------------------------------------------------------------
__global__ void __launch_bounds__(256) standardize_x_kernel(const float* __restrict__ x) {
    int col  = blockIdx.x * 8 + (threadIdx.x >> 5);
    int lane = threadIdx.x & 31;
    int tt = col >> 4;
    int n  = col & 15;

    float v[4];
    float s = 0.f;
#pragma unroll
    for (int q = 0; q < 4; q++) {
        int b = lane + q * 32;
        v[q] = x[(b * Tt + tt) * Nn + n];
        s += v[q];
    }
#pragma unroll
    for (int o = 16; o; o >>= 1) s += __shfl_xor_sync(0xffffffffu, s, o);
    float mu = s * (1.f / 128.f);

    float ss = 0.f;
#pragma unroll
    for (int q = 0; q < 4; q++) { float d = v[q] - mu; ss += d * d; }
#pragma unroll
    for (int o = 16; o; o >>= 1) ss += __shfl_xor_sync(0xffffffffu, ss, o);

    float inv = 1.f / sqrtf(ss * (1.f / 127.f));
#pragma unroll
    for (int q = 0; q < 4; q++) {
        int b = lane + q * 32;
        g_xs[n * BT + b * Tt + tt] = (v[q] - mu) * inv;
    }
}

// ---------------------------------------------------------------------------
// Kernel 2: MLP sweep, packed f32x2, 4 samples per thread (2 packed pairs).
// LayerNorms folded into the following matmuls via weight row-sums.
// Block = 128 threads, one quad per thread. grid = (K*N, 64).
// ---------------------------------------------------------------------------
__global__ void __launch_bounds__(128) mlp_kernel(
    const float* __restrict__ W1, const float* __restrict__ b1,
    const float* __restrict__ W2, const float* __restrict__ b2,
    const float* __restrict__ W3, const float* __restrict__ b3)
{
    // duplicated-packed weights in shared memory
    __shared__ float sw2f[Hh][Hh * 2];          // [o][2i..2i+1] = dup W2[o][i]  (160B rows, 16B aligned)
    __shared__ float sw1b1[Hh][4];              // {w1,w1,b1,b1} per i
    __shared__ float srs2[Hh * 2];              // dup rowsum(W2[o])
    __shared__ float sb2d[Hh * 2];              // dup b2[o]
    __shared__ float sw3d[Hh * 2];              // dup W3[i]
    __shared__ float sc[4];                     // {w3sum dup, b3 dup}

    int kn = blockIdx.x;          // k*N + n
    int n  = kn & 15;
    int k  = kn >> 4;
    int tid = threadIdx.x;

    // fill weights
    for (int idx = tid; idx < Hh * Hh; idx += 128) {
        float v = W2[kn * Hh * Hh + idx];
        int o = idx / Hh, i = idx % Hh;
        sw2f[o][2 * i] = v; sw2f[o][2 * i + 1] = v;
    }
    if (tid < Hh) {
        float w = W1[kn * Hh + tid], b = b1[kn * Hh + tid];
        sw1b1[tid][0] = w; sw1b1[tid][1] = w;
        sw1b1[tid][2] = b; sw1b1[tid][3] = b;
        float rs = 0.f;
#pragma unroll
        for (int i = 0; i < Hh; i++) rs += W2[kn * Hh * Hh + tid * Hh + i];
        srs2[2 * tid] = rs; srs2[2 * tid + 1] = rs;
        float bb = b2[kn * Hh + tid];
        sb2d[2 * tid] = bb; sb2d[2 * tid + 1] = bb;
        float w3 = W3[kn * Hh + tid];
        sw3d[2 * tid] = w3; sw3d[2 * tid + 1] = w3;
    }
    if (tid == 0) {
        float s3 = 0.f;
#pragma unroll
        for (int i = 0; i < Hh; i++) s3 += W3[kn * Hh + i];
        sc[0] = s3; sc[1] = s3;
        float bb3 = b3[kn];
        sc[2] = bb3; sc[3] = bb3;
    }
    __syncthreads();

    const float* xs = g_xs + n * BT;
    float* tout = g_t + (size_t)(k * Nn + n) * BT;

    int qi = blockIdx.y * 128 + tid;          // quad index, 0..8191
    float4 x4 = ((const float4*)xs)[qi];
    u64 xp[2];
    xp[0] = pk(x4.x, x4.y);
    xp[1] = pk(x4.z, x4.w);

    const u64 ZERO = 0ull;

    // ---- layer 1 + LN1 stats ----
    u64 h[2][Hh];
    u64 s1[2]; s1[0] = ZERO; s1[1] = ZERO;
#pragma unroll
    for (int i = 0; i < Hh; i++) {
        ulonglong2 wb = *(const ulonglong2*)&sw1b1[i][0];   // {w dup, b dup}
#pragma unroll
        for (int p = 0; p < 2; p++) {
            u64 t; FMA2(t, xp[p], wb.x, wb.y);
            t = relu2(t);
            h[p][i] = t;
            ADD2(s1[p], s1[p], t);
        }
    }
    u64 u[2], v[2];                       // u = r1 (packed), v = -mu1*r1
    const u64 c005  = pk(0.05f, 0.05f);
    const u64 cn005 = pk(-0.05f, -0.05f);
#pragma unroll
    for (int p = 0; p < 2; p++) {
        u64 mu, nmu;
        MUL2(mu,  s1[p], c005);
        MUL2(nmu, s1[p], cn005);
        u64 var = ZERO;
#pragma unroll
        for (int i = 0; i < Hh; i++) {
            u64 d; ADD2(d, h[p][i], nmu);
            FMA2(var, d, d, var);
        }
        float2 vf = up(var);
        float rx = rsqrtf(fmaf(vf.x, 0.05f, 1e-5f));
        float ry = rsqrtf(fmaf(vf.y, 0.05f, 1e-5f));
        u[p] = pk(rx, ry);
        MUL2(v[p], nmu, u[p]);
    }

    // ---- layer 2 matmul with LN1 folded; stream LN2 stats + W3 dot ----
    u64 s2[2], q2[2], d3[2];
#pragma unroll
    for (int p = 0; p < 2; p++) { s2[p] = ZERO; q2[p] = ZERO; d3[p] = ZERO; }

#pragma unroll
    for (int o = 0; o < Hh; o++) {
        const ulonglong2* wrow = (const ulonglong2*)&sw2f[o][0];
        u64 a[2]; a[0] = ZERO; a[1] = ZERO;
#pragma unroll
        for (int q = 0; q < Hh / 2; q++) {
            ulonglong2 wv = wrow[q];     // two duplicated weights
#pragma unroll
            for (int p = 0; p < 2; p++) {
                FMA2(a[p], h[p][2 * q],     wv.x, a[p]);
                FMA2(a[p], h[p][2 * q + 1], wv.y, a[p]);
            }
        }
        u64 rs = *(const u64*)&srs2[2 * o];
        u64 bo = *(const u64*)&sb2d[2 * o];
        u64 w3 = *(const u64*)&sw3d[2 * o];
#pragma unroll
        for (int p = 0; p < 2; p++) {
            u64 c; FMA2(c, v[p], rs, bo);     // -mu*r*rowsum + b2
            u64 h2; FMA2(h2, u[p], a[p], c);  // r*dot + c
            h2 = relu2(h2);
            ADD2(s2[p], s2[p], h2);
            FMA2(q2[p], h2, h2, q2[p]);
            FMA2(d3[p], h2, w3, d3[p]);
        }
    }

    // ---- LN2 fold + head ----
    u64 w3s = *(const u64*)&sc[0];
    u64 b3d = *(const u64*)&sc[2];
    float outv[4];
#pragma unroll
    for (int p = 0; p < 2; p++) {
        u64 mu2, nmu2, ex2, var2;
        MUL2(mu2,  s2[p], c005);
        MUL2(nmu2, s2[p], cn005);
        MUL2(ex2,  q2[p], c005);
        FMA2(var2, mu2, nmu2, ex2);          // E[x^2] - mu^2 (biased)
        float2 vf = up(var2);
        float rx = rsqrtf(vf.x + 1e-5f);
        float ry = rsqrtf(vf.y + 1e-5f);
        u64 r2 = pk(rx, ry);
        u64 tmp; FMA2(tmp, nmu2, w3s, d3[p]); // dot3 - mu2*w3sum
        u64 o2;  FMA2(o2, r2, tmp, b3d);
        float2 of = up(o2);
        outv[2 * p]     = of.x;
        outv[2 * p + 1] = of.y;
    }
    ((float4*)tout)[qi] = make_float4(outv[0], outv[1], outv[2], outv[3]);
}

// ---------------------------------------------------------------------------
// Kernel 3: per (k,t): standardize over b (ddof=1, eps=1e-8 on std), compute
// prod-of-marginals and prod_joint mean, write squared diff.
// grid = K*T = 2560 blocks, 128 threads. g_t layout: [k][n][j], j=b*256+t.
// ---------------------------------------------------------------------------
__global__ void __launch_bounds__(128) penalty_kernel() {
    int kt = blockIdx.x;
    int k  = kt >> 8;
    int tt = kt & 255;

    __shared__ float s[128 * 17];
    __shared__ float red[128];
    __shared__ float smu[16], srstd[16], spm[16];

    int tid = threadIdx.x;   // = b for row ops

    const float* base = g_t + (size_t)k * Nn * BT + tid * Tt + tt;
#pragma unroll
    for (int nn = 0; nn < 16; nn++)
        s[tid * 17 + nn] = base[nn * BT];
    __syncthreads();

    int n = tid & 15, g = tid >> 4;

    // mean over b per n
    float p = 0.f;
#pragma unroll
    for (int bb = 0; bb < 16; bb++) p += s[(g * 16 + bb) * 17 + n];
    red[tid] = p;
    __syncthreads();
    if (tid < 16) {
        float m = 0.f;
#pragma unroll
        for (int gg = 0; gg < 8; gg++) m += red[gg * 16 + tid];
        smu[tid] = m * (1.f / 128.f);
    }
    __syncthreads();

    // var over b per n (ddof=1), rstd = 1/(std + 1e-8)
    float mun = smu[n];
    float q2 = 0.f;
#pragma unroll
    for (int bb = 0; bb < 16; bb++) {
        float d = s[(g * 16 + bb) * 17 + n] - mun;
        q2 += d * d;
    }
    red[tid] = q2;
    __syncthreads();
    if (tid < 16) {
        float ssum = 0.f;
#pragma unroll
        for (int gg = 0; gg < 8; gg++) ssum += red[gg * 16 + tid];
        srstd[tid] = 1.f / (sqrtf(ssum * (1.f / 127.f)) + 1e-8f);
    }
    __syncthreads();

    // marginal means of standardized values
    float rn = srstd[n];
    float ps = 0.f;
#pragma unroll
    for (int bb = 0; bb < 16; bb++)
        ps += (s[(g * 16 + bb) * 17 + n] - mun) * rn;
    red[tid] = ps;
    __syncthreads();
    if (tid < 16) {
        float m = 0.f;
#pragma unroll
        for (int gg = 0; gg < 8; gg++) m += red[gg * 16 + tid];
        spm[tid] = m * (1.f / 128.f);
    }
    __syncthreads();

    // prod over n per b, mean over b
    float prod = 1.f;
#pragma unroll
    for (int nn = 0; nn < 16; nn++)
        prod *= (s[tid * 17 + nn] - smu[nn]) * srstd[nn];
    red[tid] = prod;
    __syncthreads();
#pragma unroll
    for (int off = 64; off; off >>= 1) {
        if (tid < off) red[tid] += red[tid + off];
        __syncthreads();
    }

    if (tid == 0) {
        float pj = red[0] * (1.f / 128.f);
        float pm = 1.f;
#pragma unroll
        for (int nn = 0; nn < 16; nn++) pm *= spm[nn];
        float d = pm - pj;
        g_sq[kt] = d * d;
    }
}

// ---------------------------------------------------------------------------
// Kernel 4: deterministic final reduction.
// ---------------------------------------------------------------------------
__global__ void __launch_bounds__(256) reduce_kernel(float* __restrict__ out) {
    __shared__ float red[256];
    float sum = 0.f;
    for (int i = threadIdx.x; i < KT; i += 256) sum += g_sq[i];
    red[threadIdx.x] = sum;
    __syncthreads();
#pragma unroll
    for (int off = 128; off; off >>= 1) {
        if (threadIdx.x < off) red[threadIdx.x] += red[threadIdx.x + off];
        __syncthreads();
    }
    if (threadIdx.x == 0) out[0] = red[0] * (1.f / (float)KT);
}

// ---------------------------------------------------------------------------
extern "C" void kernel_launch(void* const* d_in, const int* in_sizes, int n_in,
                              void* d_out, int out_size) {
    const float* x  = (const float*)d_in[0];
    const float* W1 = (const float*)d_in[1];
    const float* b1 = (const float*)d_in[2];
    const float* W2 = (const float*)d_in[3];
    const float* b2 = (const float*)d_in[4];
    const float* W3 = (const float*)d_in[5];
    const float* b3 = (const float*)d_in[6];

    standardize_x_kernel<<<512, 256>>>(x);

    dim3 g2(Kk * Nn, 64);
    mlp_kernel<<<g2, 128>>>(W1, b1, W2, b2, W3, b3);

    penalty_kernel<<<KT, 128>>>();

    reduce_kernel<<<1, 256>>>((float*)d_out);
}

// round 3
// speedup vs baseline: 4.7106x; 1.1530x over previous
#include <cuda_runtime.h>

// Problem constants
#define Bb   128
#define Tt   256
#define Nn   16
#define Kk   10
#define Hh   20
#define BT   32768          // Bb*Tt
#define KT   (Kk*Tt)        // 2560

typedef unsigned long long u64;

// Scratch (static device globals — no allocation)
__device__ float g_xs[Nn * BT];                    // standardized x, [n][j], 2 MB
__device__ float g_t [(size_t)Kk * Nn * BT];       // t values, [k][n][j], 20 MB
__device__ float g_sq[KT];                         // per-(k,t) squared diffs
__device__ unsigned int g_ctr;                     // completion counter (zero-init)

// ---------------- packed f32x2 helpers ----------------
__device__ __forceinline__ u64 pk(float lo, float hi) {
    u64 r; asm("mov.b64 %0,{%1,%2};" : "=l"(r) : "f"(lo), "f"(hi)); return r;
}
__device__ __forceinline__ float2 up(u64 v) {
    float2 f; asm("mov.b64 {%0,%1},%2;" : "=f"(f.x), "=f"(f.y) : "l"(v)); return f;
}
#define FMA2(d,a,b,c) asm("fma.rn.f32x2 %0,%1,%2,%3;" : "=l"(d) : "l"(a), "l"(b), "l"(c))
#define ADD2(d,a,b)   asm("add.rn.f32x2 %0,%1,%2;"    : "=l"(d) : "l"(a), "l"(b))
#define MUL2(d,a,b)   asm("mul.rn.f32x2 %0,%1,%2;"    : "=l"(d) : "l"(a), "l"(b))

__device__ __forceinline__ u64 relu2(u64 v) {
    float2 f = up(v);
    return pk(fmaxf(f.x, 0.f), fmaxf(f.y, 0.f));
}

// ---------------------------------------------------------------------------
// Kernel 1: standardize x over batch dim (per (t,n) column, ddof=1), write
// transposed into g_xs[n][b*T+t]. One warp per column, 4096 columns.
// ---------------------------------------------------------------------------
__global__ void __launch_bounds__(256) standardize_x_kernel(const float* __restrict__ x) {
    int col  = blockIdx.x * 8 + (threadIdx.x >> 5);
    int lane = threadIdx.x & 31;
    int tt = col >> 4;
    int n  = col & 15;

    float v[4];
    float s = 0.f;
#pragma unroll
    for (int q = 0; q < 4; q++) {
        int b = lane + q * 32;
        v[q] = x[(b * Tt + tt) * Nn + n];
        s += v[q];
    }
#pragma unroll
    for (int o = 16; o; o >>= 1) s += __shfl_xor_sync(0xffffffffu, s, o);
    float mu = s * (1.f / 128.f);

    float ss = 0.f;
#pragma unroll
    for (int q = 0; q < 4; q++) { float d = v[q] - mu; ss += d * d; }
#pragma unroll
    for (int o = 16; o; o >>= 1) ss += __shfl_xor_sync(0xffffffffu, ss, o);

    float inv = 1.f / sqrtf(ss * (1.f / 127.f));
#pragma unroll
    for (int q = 0; q < 4; q++) {
        int b = lane + q * 32;
        g_xs[n * BT + b * Tt + tt] = (v[q] - mu) * inv;
    }
}

// ---------------------------------------------------------------------------
// Kernel 2: MLP sweep, packed f32x2, 8 samples per thread (4 packed pairs).
// LN stats streamed (E[x^2]-mu^2), LayerNorms folded into next matmul via
// weight row-sums. Block = 128 threads. grid = (K*N, 32).
// ---------------------------------------------------------------------------
__global__ void __launch_bounds__(128) mlp_kernel(
    const float* __restrict__ W1, const float* __restrict__ b1,
    const float* __restrict__ W2, const float* __restrict__ b2,
    const float* __restrict__ W3, const float* __restrict__ b3)
{
    __shared__ __align__(16) float sw2f[Hh][Hh * 2];   // [o][2i..2i+1] = dup W2[o][i]
    __shared__ __align__(16) float sw1b1[Hh][4];       // {w1,w1,b1,b1}
    __shared__ __align__(16) float srsb[Hh][4];        // {rs,rs,b2,b2}
    __shared__ __align__(16) float sw3d[Hh * 2];       // dup W3[i]
    __shared__ __align__(16) float sc[4];              // {w3sum,w3sum,b3,b3}

    int kn = blockIdx.x;          // k*N + n
    int n  = kn & 15;
    int k  = kn >> 4;
    int tid = threadIdx.x;

    for (int idx = tid; idx < Hh * Hh; idx += 128) {
        float v = W2[kn * Hh * Hh + idx];
        int o = idx / Hh, i = idx % Hh;
        sw2f[o][2 * i] = v; sw2f[o][2 * i + 1] = v;
    }
    if (tid < Hh) {
        float w = W1[kn * Hh + tid], b = b1[kn * Hh + tid];
        sw1b1[tid][0] = w; sw1b1[tid][1] = w;
        sw1b1[tid][2] = b; sw1b1[tid][3] = b;
        float rs = 0.f;
#pragma unroll
        for (int i = 0; i < Hh; i++) rs += W2[kn * Hh * Hh + tid * Hh + i];
        float bb = b2[kn * Hh + tid];
        srsb[tid][0] = rs; srsb[tid][1] = rs;
        srsb[tid][2] = bb; srsb[tid][3] = bb;
        float w3 = W3[kn * Hh + tid];
        sw3d[2 * tid] = w3; sw3d[2 * tid + 1] = w3;
    }
    if (tid == 0) {
        float s3 = 0.f;
#pragma unroll
        for (int i = 0; i < Hh; i++) s3 += W3[kn * Hh + i];
        sc[0] = s3; sc[1] = s3;
        float bb3 = b3[kn];
        sc[2] = bb3; sc[3] = bb3;
    }
    __syncthreads();

    const float* xs = g_xs + n * BT;
    float* tout = g_t + (size_t)(k * Nn + n) * BT;

    int j0 = (blockIdx.y * 128 + tid) * 8;
    float4 xa = *(const float4*)(xs + j0);
    float4 xb = *(const float4*)(xs + j0 + 4);
    u64 xp[4];
    xp[0] = pk(xa.x, xa.y); xp[1] = pk(xa.z, xa.w);
    xp[2] = pk(xb.x, xb.y); xp[3] = pk(xb.z, xb.w);

    const u64 ZERO = 0ull;
    const u64 c005  = pk(0.05f, 0.05f);
    const u64 cn005 = pk(-0.05f, -0.05f);

    // ---- layer 1 with streamed LN1 stats ----
    u64 h[4][Hh];
    u64 s1[4], q1[4];
#pragma unroll
    for (int p = 0; p < 4; p++) { s1[p] = ZERO; q1[p] = ZERO; }
#pragma unroll
    for (int i = 0; i < Hh; i++) {
        ulonglong2 wb = *(const ulonglong2*)&sw1b1[i][0];
#pragma unroll
        for (int p = 0; p < 4; p++) {
            u64 t; FMA2(t, xp[p], wb.x, wb.y);
            t = relu2(t);
            h[p][i] = t;
            ADD2(s1[p], s1[p], t);
            FMA2(q1[p], t, t, q1[p]);
        }
    }
    u64 u[4], v[4];                 // u = r1, v = -mu1*r1 (packed)
#pragma unroll
    for (int p = 0; p < 4; p++) {
        u64 mu, nmu, ex, var;
        MUL2(mu,  s1[p], c005);
        MUL2(nmu, s1[p], cn005);
        MUL2(ex,  q1[p], c005);
        FMA2(var, mu, nmu, ex);     // E[h^2] - mu^2 (biased)
        float2 vf = up(var);
        float rx = rsqrtf(vf.x + 1e-5f);
        float ry = rsqrtf(vf.y + 1e-5f);
        u[p] = pk(rx, ry);
        MUL2(v[p], nmu, u[p]);
    }

    // ---- layer 2 matmul with LN1 folded; stream LN2 stats + W3 dot ----
    u64 s2[4], q2[4], d3[4];
#pragma unroll
    for (int p = 0; p < 4; p++) { s2[p] = ZERO; q2[p] = ZERO; d3[p] = ZERO; }

#pragma unroll 2
    for (int o = 0; o < Hh; o++) {
        const ulonglong2* wrow = (const ulonglong2*)&sw2f[o][0];
        u64 a[4]; a[0] = ZERO; a[1] = ZERO; a[2] = ZERO; a[3] = ZERO;
#pragma unroll
        for (int q = 0; q < Hh / 2; q++) {
            ulonglong2 wv = wrow[q];
#pragma unroll
            for (int p = 0; p < 4; p++) {
                FMA2(a[p], h[p][2 * q],     wv.x, a[p]);
                FMA2(a[p], h[p][2 * q + 1], wv.y, a[p]);
            }
        }
        ulonglong2 rb = *(const ulonglong2*)&srsb[o][0];   // {rs dup, b2 dup}
        u64 w3 = *(const u64*)&sw3d[2 * o];
#pragma unroll
        for (int p = 0; p < 4; p++) {
            u64 c;  FMA2(c,  v[p], rb.x, rb.y);    // -mu*r*rowsum + b2
            u64 h2; FMA2(h2, u[p], a[p], c);       // r*dot + c
            h2 = relu2(h2);
            ADD2(s2[p], s2[p], h2);
            FMA2(q2[p], h2, h2, q2[p]);
            FMA2(d3[p], h2, w3, d3[p]);
        }
    }

    // ---- LN2 fold + head ----
    u64 w3s = *(const u64*)&sc[0];
    u64 b3d = *(const u64*)&sc[2];
    float outv[8];
#pragma unroll
    for (int p = 0; p < 4; p++) {
        u64 mu2, nmu2, ex2, var2;
        MUL2(mu2,  s2[p], c005);
        MUL2(nmu2, s2[p], cn005);
        MUL2(ex2,  q2[p], c005);
        FMA2(var2, mu2, nmu2, ex2);
        float2 vf = up(var2);
        float rx = rsqrtf(vf.x + 1e-5f);
        float ry = rsqrtf(vf.y + 1e-5f);
        u64 r2 = pk(rx, ry);
        u64 tmp; FMA2(tmp, nmu2, w3s, d3[p]);
        u64 o2;  FMA2(o2, r2, tmp, b3d);
        float2 of = up(o2);
        outv[2 * p] = of.x; outv[2 * p + 1] = of.y;
    }
    *(float4*)(tout + j0)     = make_float4(outv[0], outv[1], outv[2], outv[3]);
    *(float4*)(tout + j0 + 4) = make_float4(outv[4], outv[5], outv[6], outv[7]);
}

// ---------------------------------------------------------------------------
// Kernel 3: penalty, 4 t-steps per block (float4 loads), conflict-free
// [col][b] smem layout; last block folds the final reduction.
// grid = K*T/4 = 640 blocks, 128 threads.
// ---------------------------------------------------------------------------
#define PB 4

__global__ void __launch_bounds__(128) penalty_kernel(float* __restrict__ out) {
    int bid = blockIdx.x;            // 0..639
    int k   = bid >> 6;
    int tt0 = (bid & 63) * PB;

    __shared__ float s[64][132];     // [n*4+tq][b]
    __shared__ float smu[64], sr[64], spm[64];
    __shared__ float part[PB][4];    // per-warp partial prods
    __shared__ unsigned int s_last;

    int b = threadIdx.x;

    // load: per n, one float4 (4 consecutive t)
#pragma unroll
    for (int n = 0; n < 16; n++) {
        float4 v = *(const float4*)(g_t + ((size_t)(k * 16 + n)) * BT + b * 256 + tt0);
        s[n * 4 + 0][b] = v.x;
        s[n * 4 + 1][b] = v.y;
        s[n * 4 + 2][b] = v.z;
        s[n * 4 + 3][b] = v.w;
    }
    __syncthreads();

    int col = b >> 1, hf = b & 1;

    // mean over b
    float sum = 0.f;
#pragma unroll 4
    for (int i = 0; i < 64; i++) sum += s[col][hf * 64 + i];
    sum += __shfl_xor_sync(0xffffffffu, sum, 1);
    if (hf == 0) smu[col] = sum * (1.f / 128.f);
    __syncthreads();

    // var over b (ddof=1), rstd = 1/(std+1e-8)
    float mu = smu[col];
    float q = 0.f;
#pragma unroll 4
    for (int i = 0; i < 64; i++) { float d = s[col][hf * 64 + i] - mu; q += d * d; }
    q += __shfl_xor_sync(0xffffffffu, q, 1);
    if (hf == 0) sr[col] = 1.f / (sqrtf(q * (1.f / 127.f)) + 1e-8f);
    __syncthreads();

    // marginal mean of standardized values
    float r = sr[col];
    float ps = 0.f;
#pragma unroll 4
    for (int i = 0; i < 64; i++) ps += (s[col][hf * 64 + i] - mu) * r;
    ps += __shfl_xor_sync(0xffffffffu, ps, 1);
    if (hf == 0) spm[col] = ps * (1.f / 128.f);
    __syncthreads();

    // prod over n per (b, tq); warp-reduce, then combine
    int wid = b >> 5;
#pragma unroll
    for (int tq = 0; tq < PB; tq++) {
        float prod = 1.f;
#pragma unroll
        for (int n = 0; n < 16; n++)
            prod *= (s[n * 4 + tq][b] - smu[n * 4 + tq]) * sr[n * 4 + tq];
#pragma unroll
        for (int o = 16; o; o >>= 1) prod += __shfl_xor_sync(0xffffffffu, prod, o);
        if ((b & 31) == 0) part[tq][wid] = prod;
    }
    __syncthreads();

    if (b < PB) {
        int tq = b;
        float pj = (part[tq][0] + part[tq][1] + part[tq][2] + part[tq][3]) * (1.f / 128.f);
        float pm = 1.f;
#pragma unroll
        for (int n = 0; n < 16; n++) pm *= spm[n * 4 + tq];
        float d = pm - pj;
        g_sq[k * Tt + tt0 + tq] = d * d;
    }

    // completion counter: last block reduces g_sq deterministically
    __threadfence();
    __syncthreads();
    if (b == 0) {
        unsigned int t = atomicAdd(&g_ctr, 1u);
        s_last = (t == (unsigned int)(Kk * Tt / PB - 1)) ? 1u : 0u;
    }
    __syncthreads();
    if (s_last) {
        __threadfence();
        float acc = 0.f;
        for (int i = b; i < KT; i += 128) acc += g_sq[i];
#pragma unroll
        for (int o = 16; o; o >>= 1) acc += __shfl_xor_sync(0xffffffffu, acc, o);
        if ((b & 31) == 0) part[0][b >> 5] = acc;
        __syncthreads();
        if (b == 0) {
            out[0] = (part[0][0] + part[0][1] + part[0][2] + part[0][3]) * (1.f / (float)KT);
            g_ctr = 0u;   // reset for next graph replay
        }
    }
}

// ---------------------------------------------------------------------------
extern "C" void kernel_launch(void* const* d_in, const int* in_sizes, int n_in,
                              void* d_out, int out_size) {
    const float* x  = (const float*)d_in[0];
    const float* W1 = (const float*)d_in[1];
    const float* b1 = (const float*)d_in[2];
    const float* W2 = (const float*)d_in[3];
    const float* b2 = (const float*)d_in[4];
    const float* W3 = (const float*)d_in[5];
    const float* b3 = (const float*)d_in[6];

    standardize_x_kernel<<<512, 256>>>(x);

    dim3 g2(Kk * Nn, 32);
    mlp_kernel<<<g2, 128>>>(W1, b1, W2, b2, W3, b3);

    penalty_kernel<<<KT / PB, 128>>>((float*)d_out);
}

// round 4
// speedup vs baseline: 4.8759x; 1.0351x over previous
#include <cuda_runtime.h>

// Problem constants
#define Bb   128
#define Tt   256
#define Nn   16
#define Kk   10
#define Hh   20
#define BT   32768          // Bb*Tt
#define KT   (Kk*Tt)        // 2560

typedef unsigned long long u64;

// Scratch (static device globals — no allocation)
__device__ float g_xs[Nn * BT];                    // standardized x, [n][j], 2 MB
__device__ float g_t [(size_t)Kk * Nn * BT];       // t values, [k][n][j], 20 MB
__device__ float g_sq[KT];                         // per-(k,t) squared diffs
__device__ unsigned int g_ctr;                     // completion counter (zero-init)

// ---------------- packed f32x2 helpers ----------------
__device__ __forceinline__ u64 pk(float lo, float hi) {
    u64 r; asm("mov.b64 %0,{%1,%2};" : "=l"(r) : "f"(lo), "f"(hi)); return r;
}
__device__ __forceinline__ float2 up(u64 v) {
    float2 f; asm("mov.b64 {%0,%1},%2;" : "=f"(f.x), "=f"(f.y) : "l"(v)); return f;
}
#define FMA2(d,a,b,c) asm("fma.rn.f32x2 %0,%1,%2,%3;" : "=l"(d) : "l"(a), "l"(b), "l"(c))
#define ADD2(d,a,b)   asm("add.rn.f32x2 %0,%1,%2;"    : "=l"(d) : "l"(a), "l"(b))
#define MUL2(d,a,b)   asm("mul.rn.f32x2 %0,%1,%2;"    : "=l"(d) : "l"(a), "l"(b))

__device__ __forceinline__ u64 relu2(u64 v) {
    float2 f = up(v);
    return pk(fmaxf(f.x, 0.f), fmaxf(f.y, 0.f));
}

// ---------------------------------------------------------------------------
// Kernel 1: standardize x over batch dim (per (t,n) column, ddof=1), write
// transposed into g_xs[n][b*T+t].
// One warp handles 32 consecutive t x 4 consecutive n. Two streaming passes:
// pass 1 accumulates sum/sumsq (float4 over n, coalesced), pass 2 reloads
// (L2-hot) and writes 128B-coalesced rows into each n-plane.
// grid = 32 blocks x 32 threads.
// ---------------------------------------------------------------------------
__global__ void __launch_bounds__(32) standardize_x_kernel(const float* __restrict__ x) {
    int w  = blockIdx.x;                 // 0..31
    int n0 = (w & 3) * 4;
    int tt = (w >> 2) * 32 + threadIdx.x;

    float s0 = 0.f, s1 = 0.f, s2 = 0.f, s3 = 0.f;
    float q0 = 0.f, q1 = 0.f, q2 = 0.f, q3 = 0.f;

#pragma unroll 8
    for (int b = 0; b < Bb; b++) {
        float4 v = *(const float4*)(x + ((size_t)(b * Tt + tt)) * Nn + n0);
        s0 += v.x; q0 = fmaf(v.x, v.x, q0);
        s1 += v.y; q1 = fmaf(v.y, v.y, q1);
        s2 += v.z; q2 = fmaf(v.z, v.z, q2);
        s3 += v.w; q3 = fmaf(v.w, v.w, q3);
    }

    float mu0 = s0 * (1.f / 128.f), mu1 = s1 * (1.f / 128.f);
    float mu2 = s2 * (1.f / 128.f), mu3 = s3 * (1.f / 128.f);
    float i0 = 1.f / sqrtf((q0 - s0 * mu0) * (1.f / 127.f));
    float i1 = 1.f / sqrtf((q1 - s1 * mu1) * (1.f / 127.f));
    float i2 = 1.f / sqrtf((q2 - s2 * mu2) * (1.f / 127.f));
    float i3 = 1.f / sqrtf((q3 - s3 * mu3) * (1.f / 127.f));

    float* p0 = g_xs + (n0 + 0) * BT + tt;
    float* p1 = g_xs + (n0 + 1) * BT + tt;
    float* p2 = g_xs + (n0 + 2) * BT + tt;
    float* p3 = g_xs + (n0 + 3) * BT + tt;

#pragma unroll 4
    for (int b = 0; b < Bb; b++) {
        float4 v = *(const float4*)(x + ((size_t)(b * Tt + tt)) * Nn + n0);
        p0[b * Tt] = (v.x - mu0) * i0;
        p1[b * Tt] = (v.y - mu1) * i1;
        p2[b * Tt] = (v.z - mu2) * i2;
        p3[b * Tt] = (v.w - mu3) * i3;
    }
}

// ---------------------------------------------------------------------------
// Kernel 2: MLP sweep, packed f32x2, 8 samples per thread (4 packed pairs).
// LN1 applied in-register once; layer-2 accumulators initialized with b2;
// LN2 folded into the head via streamed stats. Block = 128. grid = (K*N, 32).
// ---------------------------------------------------------------------------
__global__ void __launch_bounds__(128) mlp_kernel(
    const float* __restrict__ W1, const float* __restrict__ b1,
    const float* __restrict__ W2, const float* __restrict__ b2,
    const float* __restrict__ W3, const float* __restrict__ b3)
{
    __shared__ __align__(16) float sw2f[Hh][Hh * 2];   // [o][2i..2i+1] = dup W2[o][i]
    __shared__ __align__(16) float sw1b1[Hh][4];       // {w1,w1,b1,b1}
    __shared__ __align__(16) float sb2w3[Hh][4];       // {b2,b2,w3,w3}
    __shared__ __align__(16) float sc[4];              // {w3sum,w3sum,b3,b3}

    int kn = blockIdx.x;          // k*N + n
    int n  = kn & 15;
    int k  = kn >> 4;
    int tid = threadIdx.x;

    for (int idx = tid; idx < Hh * Hh; idx += 128) {
        float v = W2[kn * Hh * Hh + idx];
        int o = idx / Hh, i = idx % Hh;
        sw2f[o][2 * i] = v; sw2f[o][2 * i + 1] = v;
    }
    if (tid < Hh) {
        float w = W1[kn * Hh + tid], b = b1[kn * Hh + tid];
        sw1b1[tid][0] = w; sw1b1[tid][1] = w;
        sw1b1[tid][2] = b; sw1b1[tid][3] = b;
        float bb = b2[kn * Hh + tid];
        float w3 = W3[kn * Hh + tid];
        sb2w3[tid][0] = bb; sb2w3[tid][1] = bb;
        sb2w3[tid][2] = w3; sb2w3[tid][3] = w3;
    }
    if (tid == 0) {
        float s3 = 0.f;
#pragma unroll
        for (int i = 0; i < Hh; i++) s3 += W3[kn * Hh + i];
        sc[0] = s3; sc[1] = s3;
        float bb3 = b3[kn];
        sc[2] = bb3; sc[3] = bb3;
    }
    __syncthreads();

    const float* xs = g_xs + n * BT;
    float* tout = g_t + (size_t)(k * Nn + n) * BT;

    int j0 = (blockIdx.y * 128 + tid) * 8;
    float4 xa = *(const float4*)(xs + j0);
    float4 xb = *(const float4*)(xs + j0 + 4);
    u64 xp[4];
    xp[0] = pk(xa.x, xa.y); xp[1] = pk(xa.z, xa.w);
    xp[2] = pk(xb.x, xb.y); xp[3] = pk(xb.z, xb.w);

    const u64 ZERO = 0ull;
    const u64 c005  = pk(0.05f, 0.05f);
    const u64 cn005 = pk(-0.05f, -0.05f);

    // ---- layer 1 with streamed LN1 stats ----
    u64 h[4][Hh];
    u64 s1[4], q1[4];
#pragma unroll
    for (int p = 0; p < 4; p++) { s1[p] = ZERO; q1[p] = ZERO; }
#pragma unroll
    for (int i = 0; i < Hh; i++) {
        ulonglong2 wb = *(const ulonglong2*)&sw1b1[i][0];
#pragma unroll
        for (int p = 0; p < 4; p++) {
            u64 t; FMA2(t, xp[p], wb.x, wb.y);
            t = relu2(t);
            h[p][i] = t;
            ADD2(s1[p], s1[p], t);
            FMA2(q1[p], t, t, q1[p]);
        }
    }
    // LN1: normalize h in place (one FMA each: h*r + (-mu*r))
#pragma unroll
    for (int p = 0; p < 4; p++) {
        u64 mu, nmu, ex, var;
        MUL2(mu,  s1[p], c005);
        MUL2(nmu, s1[p], cn005);
        MUL2(ex,  q1[p], c005);
        FMA2(var, mu, nmu, ex);     // E[h^2] - mu^2 (biased)
        float2 vf = up(var);
        float rx = rsqrtf(vf.x + 1e-5f);
        float ry = rsqrtf(vf.y + 1e-5f);
        u64 r1 = pk(rx, ry);
        u64 v1; MUL2(v1, nmu, r1);  // -mu*r
#pragma unroll
        for (int i = 0; i < Hh; i++)
            FMA2(h[p][i], h[p][i], r1, v1);
    }

    // ---- layer 2 matmul; accumulators start at b2; stream LN2 stats + W3 dot ----
    u64 s2[4], q2[4], d3[4];
#pragma unroll
    for (int p = 0; p < 4; p++) { s2[p] = ZERO; q2[p] = ZERO; d3[p] = ZERO; }

#pragma unroll 2
    for (int o = 0; o < Hh; o++) {
        const ulonglong2* wrow = (const ulonglong2*)&sw2f[o][0];
        ulonglong2 bw = *(const ulonglong2*)&sb2w3[o][0];   // {b2 dup, w3 dup}
        u64 a[4];
        a[0] = bw.x; a[1] = bw.x; a[2] = bw.x; a[3] = bw.x;
#pragma unroll
        for (int q = 0; q < Hh / 2; q++) {
            ulonglong2 wv = wrow[q];
#pragma unroll
            for (int p = 0; p < 4; p++) {
                FMA2(a[p], h[p][2 * q],     wv.x, a[p]);
                FMA2(a[p], h[p][2 * q + 1], wv.y, a[p]);
            }
        }
#pragma unroll
        for (int p = 0; p < 4; p++) {
            u64 h2 = relu2(a[p]);
            ADD2(s2[p], s2[p], h2);
            FMA2(q2[p], h2, h2, q2[p]);
            FMA2(d3[p], h2, bw.y, d3[p]);
        }
    }

    // ---- LN2 fold + head ----
    u64 w3s = *(const u64*)&sc[0];
    u64 b3d = *(const u64*)&sc[2];
    float outv[8];
#pragma unroll
    for (int p = 0; p < 4; p++) {
        u64 mu2, nmu2, ex2, var2;
        MUL2(mu2,  s2[p], c005);
        MUL2(nmu2, s2[p], cn005);
        MUL2(ex2,  q2[p], c005);
        FMA2(var2, mu2, nmu2, ex2);
        float2 vf = up(var2);
        float rx = rsqrtf(vf.x + 1e-5f);
        float ry = rsqrtf(vf.y + 1e-5f);
        u64 r2 = pk(rx, ry);
        u64 tmp; FMA2(tmp, nmu2, w3s, d3[p]);
        u64 o2;  FMA2(o2, r2, tmp, b3d);
        float2 of = up(o2);
        outv[2 * p] = of.x; outv[2 * p + 1] = of.y;
    }
    *(float4*)(tout + j0)     = make_float4(outv[0], outv[1], outv[2], outv[3]);
    *(float4*)(tout + j0 + 4) = make_float4(outv[4], outv[5], outv[6], outv[7]);
}

// ---------------------------------------------------------------------------
// Kernel 3: penalty, 4 t-steps per block (float4 loads), conflict-free
// [col][b] smem layout; last block folds the final reduction.
// grid = K*T/4 = 640 blocks, 128 threads.
// ---------------------------------------------------------------------------
#define PB 4

__global__ void __launch_bounds__(128) penalty_kernel(float* __restrict__ out) {
    int bid = blockIdx.x;            // 0..639
    int k   = bid >> 6;
    int tt0 = (bid & 63) * PB;

    __shared__ float s[64][132];     // [n*4+tq][b]
    __shared__ float smu[64], sr[64], spm[64];
    __shared__ float part[PB][4];    // per-warp partial prods
    __shared__ unsigned int s_last;

    int b = threadIdx.x;

#pragma unroll
    for (int n = 0; n < 16; n++) {
        float4 v = *(const float4*)(g_t + ((size_t)(k * 16 + n)) * BT + b * 256 + tt0);
        s[n * 4 + 0][b] = v.x;
        s[n * 4 + 1][b] = v.y;
        s[n * 4 + 2][b] = v.z;
        s[n * 4 + 3][b] = v.w;
    }
    __syncthreads();

    int col = b >> 1, hf = b & 1;

    // mean over b
    float sum = 0.f;
#pragma unroll 4
    for (int i = 0; i < 64; i++) sum += s[col][hf * 64 + i];
    sum += __shfl_xor_sync(0xffffffffu, sum, 1);
    if (hf == 0) smu[col] = sum * (1.f / 128.f);
    __syncthreads();

    // var over b (ddof=1), rstd = 1/(std+1e-8)
    float mu = smu[col];
    float q = 0.f;
#pragma unroll 4
    for (int i = 0; i < 64; i++) { float d = s[col][hf * 64 + i] - mu; q += d * d; }
    q += __shfl_xor_sync(0xffffffffu, q, 1);
    if (hf == 0) sr[col] = 1.f / (sqrtf(q * (1.f / 127.f)) + 1e-8f);
    __syncthreads();

    // marginal mean of standardized values
    float r = sr[col];
    float ps = 0.f;
#pragma unroll 4
    for (int i = 0; i < 64; i++) ps += (s[col][hf * 64 + i] - mu) * r;
    ps += __shfl_xor_sync(0xffffffffu, ps, 1);
    if (hf == 0) spm[col] = ps * (1.f / 128.f);
    __syncthreads();

    // prod over n per (b, tq); warp-reduce, then combine
    int wid = b >> 5;
#pragma unroll
    for (int tq = 0; tq < PB; tq++) {
        float prod = 1.f;
#pragma unroll
        for (int n = 0; n < 16; n++)
            prod *= (s[n * 4 + tq][b] - smu[n * 4 + tq]) * sr[n * 4 + tq];
#pragma unroll
        for (int o = 16; o; o >>= 1) prod += __shfl_xor_sync(0xffffffffu, prod, o);
        if ((b & 31) == 0) part[tq][wid] = prod;
    }
    __syncthreads();

    if (b < PB) {
        int tq = b;
        float pj = (part[tq][0] + part[tq][1] + part[tq][2] + part[tq][3]) * (1.f / 128.f);
        float pm = 1.f;
#pragma unroll
        for (int n = 0; n < 16; n++) pm *= spm[n * 4 + tq];
        float d = pm - pj;
        g_sq[k * Tt + tt0 + tq] = d * d;
    }

    // completion counter: last block reduces g_sq deterministically
    __threadfence();
    __syncthreads();
    if (b == 0) {
        unsigned int t = atomicAdd(&g_ctr, 1u);
        s_last = (t == (unsigned int)(Kk * Tt / PB - 1)) ? 1u : 0u;
    }
    __syncthreads();
    if (s_last) {
        __threadfence();
        float acc = 0.f;
        for (int i = b; i < KT; i += 128) acc += g_sq[i];
#pragma unroll
        for (int o = 16; o; o >>= 1) acc += __shfl_xor_sync(0xffffffffu, acc, o);
        if ((b & 31) == 0) part[0][b >> 5] = acc;
        __syncthreads();
        if (b == 0) {
            out[0] = (part[0][0] + part[0][1] + part[0][2] + part[0][3]) * (1.f / (float)KT);
            g_ctr = 0u;   // reset for next graph replay
        }
    }
}

// ---------------------------------------------------------------------------
extern "C" void kernel_launch(void* const* d_in, const int* in_sizes, int n_in,
                              void* d_out, int out_size) {
    const float* x  = (const float*)d_in[0];
    const float* W1 = (const float*)d_in[1];
    const float* b1 = (const float*)d_in[2];
    const float* W2 = (const float*)d_in[3];
    const float* b2 = (const float*)d_in[4];
    const float* W3 = (const float*)d_in[5];
    const float* b3 = (const float*)d_in[6];

    standardize_x_kernel<<<32, 32>>>(x);

    dim3 g2(Kk * Nn, 32);
    mlp_kernel<<<g2, 128>>>(W1, b1, W2, b2, W3, b3);

    penalty_kernel<<<KT / PB, 128>>>((float*)d_out);
}

// round 5
// speedup vs baseline: 5.1659x; 1.0595x over previous
#include <cuda_runtime.h>

// Problem constants
#define Bb   128
#define Tt   256
#define Nn   16
#define Kk   10
#define Hh   20
#define BT   32768          // Bb*Tt
#define KT   (Kk*Tt)        // 2560

typedef unsigned long long u64;

// Scratch (static device globals — no allocation)
__device__ float g_xs[Nn * BT];                    // standardized x, [n][j], 2 MB
__device__ float g_t [(size_t)Kk * Nn * BT];       // t values, [k][n][j], 20 MB
__device__ float g_sq[KT];                         // per-(k,t) squared diffs
__device__ float g_mu[Nn * Tt];                    // per-(t,n) mean, [n][t]
__device__ float g_ri[Nn * Tt];                    // per-(t,n) 1/std,  [n][t]
__device__ unsigned int g_ctr;                     // completion counter (zero-init)

// ---------------- packed f32x2 helpers ----------------
__device__ __forceinline__ u64 pk(float lo, float hi) {
    u64 r; asm("mov.b64 %0,{%1,%2};" : "=l"(r) : "f"(lo), "f"(hi)); return r;
}
__device__ __forceinline__ float2 up(u64 v) {
    float2 f; asm("mov.b64 {%0,%1},%2;" : "=f"(f.x), "=f"(f.y) : "l"(v)); return f;
}
#define FMA2(d,a,b,c) asm("fma.rn.f32x2 %0,%1,%2,%3;" : "=l"(d) : "l"(a), "l"(b), "l"(c))
#define ADD2(d,a,b)   asm("add.rn.f32x2 %0,%1,%2;"    : "=l"(d) : "l"(a), "l"(b))
#define MUL2(d,a,b)   asm("mul.rn.f32x2 %0,%1,%2;"    : "=l"(d) : "l"(a), "l"(b))

__device__ __forceinline__ u64 relu2(u64 v) {
    float2 f = up(v);
    return pk(fmaxf(f.x, 0.f), fmaxf(f.y, 0.f));
}

// ---------------------------------------------------------------------------
// Kernel 1a: per-(t,n) column stats over b (ddof=1). 4 threads per column,
// each sums 32 b values; coalesced 128B warp loads; smem combine.
// grid = 32 blocks x 512 threads. Stats written in [n][t] layout.
// ---------------------------------------------------------------------------
__global__ void __launch_bounds__(512) stats_kernel(const float* __restrict__ x) {
    __shared__ float ss[4][128], sq[4][128];
    int q  = threadIdx.x >> 7;            // 0..3 (b sub-range)
    int cl = threadIdx.x & 127;
    int gc = blockIdx.x * 128 + cl;       // global column = t*16+n

    float s = 0.f, qq = 0.f;
#pragma unroll 8
    for (int b = q * 32; b < q * 32 + 32; b++) {
        float v = x[b * 4096 + gc];
        s += v; qq = fmaf(v, v, qq);
    }
    ss[q][cl] = s; sq[q][cl] = qq;
    __syncthreads();
    if (threadIdx.x < 128) {
        float S = ss[0][cl] + ss[1][cl] + ss[2][cl] + ss[3][cl];
        float Q = sq[0][cl] + sq[1][cl] + sq[2][cl] + sq[3][cl];
        float mu = S * (1.f / 128.f);
        float ri = 1.f / sqrtf((Q - S * mu) * (1.f / 127.f));
        int t = gc >> 4, n = gc & 15;
        g_mu[n * Tt + t] = mu;
        g_ri[n * Tt + t] = ri;
    }
}

// ---------------------------------------------------------------------------
// Kernel 1b: transpose + normalize: x[b][t][n] -> g_xs[n][b*256+t].
// 8b x 32t x 16n smem tile; coalesced loads and 64B-contiguous stores.
// grid = (16 b-chunks, 8 t-chunks), 256 threads.
// ---------------------------------------------------------------------------
__global__ void __launch_bounds__(256) transpose_kernel(const float* __restrict__ x) {
    __shared__ float tile[8][16][33];   // [b][n][t]
    int b0 = blockIdx.x * 8;
    int t0 = blockIdx.y * 32;
    int tid = threadIdx.x;

    // load 4096 floats (1024 float4, 4 per thread), fully coalesced
#pragma unroll
    for (int r = 0; r < 4; r++) {
        int f  = r * 256 + tid;
        int n4 = f & 3;
        int tl = (f >> 2) & 31;
        int bl = f >> 7;
        float4 v = *(const float4*)(x + ((size_t)((b0 + bl) * Tt + t0 + tl)) * Nn + n4 * 4);
        tile[bl][n4 * 4 + 0][tl] = v.x;
        tile[bl][n4 * 4 + 1][tl] = v.y;
        tile[bl][n4 * 4 + 2][tl] = v.z;
        tile[bl][n4 * 4 + 3][tl] = v.w;
    }
    __syncthreads();

    // output: thread = (n, bl, half); writes 16 consecutive t (4x float4)
    int half = tid & 1;
    int pair = tid >> 1;       // 0..127
    int bl = pair & 7;
    int n  = pair >> 3;

    const float* pm = g_mu + n * Tt + t0 + half * 16;
    const float* pr = g_ri + n * Tt + t0 + half * 16;
    float* outp = g_xs + n * BT + (b0 + bl) * Tt + t0 + half * 16;

#pragma unroll
    for (int r = 0; r < 4; r++) {
        float4 m  = *(const float4*)(pm + r * 4);
        float4 ir = *(const float4*)(pr + r * 4);
        int tl = half * 16 + r * 4;
        float4 o;
        o.x = (tile[bl][n][tl + 0] - m.x) * ir.x;
        o.y = (tile[bl][n][tl + 1] - m.y) * ir.y;
        o.z = (tile[bl][n][tl + 2] - m.z) * ir.z;
        o.w = (tile[bl][n][tl + 3] - m.w) * ir.w;
        *(float4*)(outp + r * 4) = o;
    }
}

// ---------------------------------------------------------------------------
// Kernel 2: MLP sweep, packed f32x2, 8 samples per thread (4 packed pairs).
// LN1 applied in-register once; layer-2 accumulators initialized with b2;
// LN2 folded into the head via streamed stats. Block = 128. grid = (K*N, 32).
// ---------------------------------------------------------------------------
__global__ void __launch_bounds__(128) mlp_kernel(
    const float* __restrict__ W1, const float* __restrict__ b1,
    const float* __restrict__ W2, const float* __restrict__ b2,
    const float* __restrict__ W3, const float* __restrict__ b3)
{
    __shared__ __align__(16) float sw2f[Hh][Hh * 2];   // [o][2i..2i+1] = dup W2[o][i]
    __shared__ __align__(16) float sw1b1[Hh][4];       // {w1,w1,b1,b1}
    __shared__ __align__(16) float sb2w3[Hh][4];       // {b2,b2,w3,w3}
    __shared__ __align__(16) float sc[4];              // {w3sum,w3sum,b3,b3}

    int kn = blockIdx.x;          // k*N + n
    int n  = kn & 15;
    int k  = kn >> 4;
    int tid = threadIdx.x;

    for (int idx = tid; idx < Hh * Hh; idx += 128) {
        float v = W2[kn * Hh * Hh + idx];
        int o = idx / Hh, i = idx % Hh;
        sw2f[o][2 * i] = v; sw2f[o][2 * i + 1] = v;
    }
    if (tid < Hh) {
        float w = W1[kn * Hh + tid], b = b1[kn * Hh + tid];
        sw1b1[tid][0] = w; sw1b1[tid][1] = w;
        sw1b1[tid][2] = b; sw1b1[tid][3] = b;
        float bb = b2[kn * Hh + tid];
        float w3 = W3[kn * Hh + tid];
        sb2w3[tid][0] = bb; sb2w3[tid][1] = bb;
        sb2w3[tid][2] = w3; sb2w3[tid][3] = w3;
    }
    if (tid == 0) {
        float s3 = 0.f;
#pragma unroll
        for (int i = 0; i < Hh; i++) s3 += W3[kn * Hh + i];
        sc[0] = s3; sc[1] = s3;
        float bb3 = b3[kn];
        sc[2] = bb3; sc[3] = bb3;
    }
    __syncthreads();

    const float* xs = g_xs + n * BT;
    float* tout = g_t + (size_t)(k * Nn + n) * BT;

    int j0 = (blockIdx.y * 128 + tid) * 8;
    float4 xa = *(const float4*)(xs + j0);
    float4 xb = *(const float4*)(xs + j0 + 4);
    u64 xp[4];
    xp[0] = pk(xa.x, xa.y); xp[1] = pk(xa.z, xa.w);
    xp[2] = pk(xb.x, xb.y); xp[3] = pk(xb.z, xb.w);

    const u64 ZERO = 0ull;
    const u64 c005  = pk(0.05f, 0.05f);
    const u64 cn005 = pk(-0.05f, -0.05f);

    // ---- layer 1 with streamed LN1 stats ----
    u64 h[4][Hh];
    u64 s1[4], q1[4];
#pragma unroll
    for (int p = 0; p < 4; p++) { s1[p] = ZERO; q1[p] = ZERO; }
#pragma unroll
    for (int i = 0; i < Hh; i++) {
        ulonglong2 wb = *(const ulonglong2*)&sw1b1[i][0];
#pragma unroll
        for (int p = 0; p < 4; p++) {
            u64 t; FMA2(t, xp[p], wb.x, wb.y);
            t = relu2(t);
            h[p][i] = t;
            ADD2(s1[p], s1[p], t);
            FMA2(q1[p], t, t, q1[p]);
        }
    }
    // LN1: normalize h in place (one FMA each: h*r + (-mu*r))
#pragma unroll
    for (int p = 0; p < 4; p++) {
        u64 mu, nmu, ex, var;
        MUL2(mu,  s1[p], c005);
        MUL2(nmu, s1[p], cn005);
        MUL2(ex,  q1[p], c005);
        FMA2(var, mu, nmu, ex);     // E[h^2] - mu^2 (biased)
        float2 vf = up(var);
        float rx = rsqrtf(vf.x + 1e-5f);
        float ry = rsqrtf(vf.y + 1e-5f);
        u64 r1 = pk(rx, ry);
        u64 v1; MUL2(v1, nmu, r1);  // -mu*r
#pragma unroll
        for (int i = 0; i < Hh; i++)
            FMA2(h[p][i], h[p][i], r1, v1);
    }

    // ---- layer 2 matmul; accumulators start at b2; stream LN2 stats + W3 dot ----
    u64 s2[4], q2[4], d3[4];
#pragma unroll
    for (int p = 0; p < 4; p++) { s2[p] = ZERO; q2[p] = ZERO; d3[p] = ZERO; }

#pragma unroll 2
    for (int o = 0; o < Hh; o++) {
        const ulonglong2* wrow = (const ulonglong2*)&sw2f[o][0];
        ulonglong2 bw = *(const ulonglong2*)&sb2w3[o][0];   // {b2 dup, w3 dup}
        u64 a[4];
        a[0] = bw.x; a[1] = bw.x; a[2] = bw.x; a[3] = bw.x;
#pragma unroll
        for (int q = 0; q < Hh / 2; q++) {
            ulonglong2 wv = wrow[q];
#pragma unroll
            for (int p = 0; p < 4; p++) {
                FMA2(a[p], h[p][2 * q],     wv.x, a[p]);
                FMA2(a[p], h[p][2 * q + 1], wv.y, a[p]);
            }
        }
#pragma unroll
        for (int p = 0; p < 4; p++) {
            u64 h2 = relu2(a[p]);
            ADD2(s2[p], s2[p], h2);
            FMA2(q2[p], h2, h2, q2[p]);
            FMA2(d3[p], h2, bw.y, d3[p]);
        }
    }

    // ---- LN2 fold + head ----
    u64 w3s = *(const u64*)&sc[0];
    u64 b3d = *(const u64*)&sc[2];
    float outv[8];
#pragma unroll
    for (int p = 0; p < 4; p++) {
        u64 mu2, nmu2, ex2, var2;
        MUL2(mu2,  s2[p], c005);
        MUL2(nmu2, s2[p], cn005);
        MUL2(ex2,  q2[p], c005);
        FMA2(var2, mu2, nmu2, ex2);
        float2 vf = up(var2);
        float rx = rsqrtf(vf.x + 1e-5f);
        float ry = rsqrtf(vf.y + 1e-5f);
        u64 r2 = pk(rx, ry);
        u64 tmp; FMA2(tmp, nmu2, w3s, d3[p]);
        u64 o2;  FMA2(o2, r2, tmp, b3d);
        float2 of = up(o2);
        outv[2 * p] = of.x; outv[2 * p + 1] = of.y;
    }
    *(float4*)(tout + j0)     = make_float4(outv[0], outv[1], outv[2], outv[3]);
    *(float4*)(tout + j0 + 4) = make_float4(outv[4], outv[5], outv[6], outv[7]);
}

// ---------------------------------------------------------------------------
// Kernel 3: penalty, 4 t-steps per block (float4 loads), conflict-free
// [col][b] smem layout; last block folds the final reduction.
// grid = K*T/4 = 640 blocks, 128 threads.
// ---------------------------------------------------------------------------
#define PB 4

__global__ void __launch_bounds__(128) penalty_kernel(float* __restrict__ out) {
    int bid = blockIdx.x;            // 0..639
    int k   = bid >> 6;
    int tt0 = (bid & 63) * PB;

    __shared__ float s[64][132];     // [n*4+tq][b]
    __shared__ float smu[64], sr[64], spm[64];
    __shared__ float part[PB][4];    // per-warp partial prods
    __shared__ unsigned int s_last;

    int b = threadIdx.x;

#pragma unroll
    for (int n = 0; n < 16; n++) {
        float4 v = *(const float4*)(g_t + ((size_t)(k * 16 + n)) * BT + b * 256 + tt0);
        s[n * 4 + 0][b] = v.x;
        s[n * 4 + 1][b] = v.y;
        s[n * 4 + 2][b] = v.z;
        s[n * 4 + 3][b] = v.w;
    }
    __syncthreads();

    int col = b >> 1, hf = b & 1;

    // mean over b
    float sum = 0.f;
#pragma unroll 4
    for (int i = 0; i < 64; i++) sum += s[col][hf * 64 + i];
    sum += __shfl_xor_sync(0xffffffffu, sum, 1);
    if (hf == 0) smu[col] = sum * (1.f / 128.f);
    __syncthreads();

    // var over b (ddof=1), rstd = 1/(std+1e-8)
    float mu = smu[col];
    float q = 0.f;
#pragma unroll 4
    for (int i = 0; i < 64; i++) { float d = s[col][hf * 64 + i] - mu; q += d * d; }
    q += __shfl_xor_sync(0xffffffffu, q, 1);
    if (hf == 0) sr[col] = 1.f / (sqrtf(q * (1.f / 127.f)) + 1e-8f);
    __syncthreads();

    // marginal mean of standardized values
    float r = sr[col];
    float ps = 0.f;
#pragma unroll 4
    for (int i = 0; i < 64; i++) ps += (s[col][hf * 64 + i] - mu) * r;
    ps += __shfl_xor_sync(0xffffffffu, ps, 1);
    if (hf == 0) spm[col] = ps * (1.f / 128.f);
    __syncthreads();

    // prod over n per (b, tq); warp-reduce, then combine
    int wid = b >> 5;
#pragma unroll
    for (int tq = 0; tq < PB; tq++) {
        float prod = 1.f;
#pragma unroll
        for (int n = 0; n < 16; n++)
            prod *= (s[n * 4 + tq][b] - smu[n * 4 + tq]) * sr[n * 4 + tq];
#pragma unroll
        for (int o = 16; o; o >>= 1) prod += __shfl_xor_sync(0xffffffffu, prod, o);
        if ((b & 31) == 0) part[tq][wid] = prod;
    }
    __syncthreads();

    if (b < PB) {
        int tq = b;
        float pj = (part[tq][0] + part[tq][1] + part[tq][2] + part[tq][3]) * (1.f / 128.f);
        float pm = 1.f;
#pragma unroll
        for (int n = 0; n < 16; n++) pm *= spm[n * 4 + tq];
        float d = pm - pj;
        g_sq[k * Tt + tt0 + tq] = d * d;
    }

    // completion counter: last block reduces g_sq deterministically
    __threadfence();
    __syncthreads();
    if (b == 0) {
        unsigned int t = atomicAdd(&g_ctr, 1u);
        s_last = (t == (unsigned int)(Kk * Tt / PB - 1)) ? 1u : 0u;
    }
    __syncthreads();
    if (s_last) {
        __threadfence();
        float acc = 0.f;
        for (int i = b; i < KT; i += 128) acc += g_sq[i];
#pragma unroll
        for (int o = 16; o; o >>= 1) acc += __shfl_xor_sync(0xffffffffu, acc, o);
        if ((b & 31) == 0) part[0][b >> 5] = acc;
        __syncthreads();
        if (b == 0) {
            out[0] = (part[0][0] + part[0][1] + part[0][2] + part[0][3]) * (1.f / (float)KT);
            g_ctr = 0u;   // reset for next graph replay
        }
    }
}

// ---------------------------------------------------------------------------
extern "C" void kernel_launch(void* const* d_in, const int* in_sizes, int n_in,
                              void* d_out, int out_size) {
    const float* x  = (const float*)d_in[0];
    const float* W1 = (const float*)d_in[1];
    const float* b1 = (const float*)d_in[2];
    const float* W2 = (const float*)d_in[3];
    const float* b2 = (const float*)d_in[4];
    const float* W3 = (const float*)d_in[5];
    const float* b3 = (const float*)d_in[6];

    stats_kernel<<<32, 512>>>(x);

    dim3 g1(16, 8);
    transpose_kernel<<<g1, 256>>>(x);

    dim3 g2(Kk * Nn, 32);
    mlp_kernel<<<g2, 128>>>(W1, b1, W2, b2, W3, b3);

    penalty_kernel<<<KT / PB, 128>>>((float*)d_out);
}

// round 6
// speedup vs baseline: 5.2612x; 1.0185x over previous
#include <cuda_runtime.h>

// Problem constants
#define Bb   128
#define Tt   256
#define Nn   16
#define Kk   10
#define Hh   20
#define BT   32768          // Bb*Tt
#define KT   (Kk*Tt)        // 2560

typedef unsigned long long u64;

// Scratch (static device globals — no allocation)
__device__ float g_xs[Nn * BT];                    // standardized x, [n][j], 2 MB
__device__ float g_t [(size_t)Kk * Nn * BT];       // t values, [k][n][j], 20 MB
__device__ float g_sq[KT];                         // per-(k,t) squared diffs
__device__ float g_mu[Nn * Tt];                    // per-(t,n) mean, [n][t]
__device__ float g_ri[Nn * Tt];                    // per-(t,n) 1/std,  [n][t]
__device__ unsigned int g_ctr;                     // completion counter (zero-init)

// ---------------- packed f32x2 helpers ----------------
__device__ __forceinline__ u64 pk(float lo, float hi) {
    u64 r; asm("mov.b64 %0,{%1,%2};" : "=l"(r) : "f"(lo), "f"(hi)); return r;
}
__device__ __forceinline__ float2 up(u64 v) {
    float2 f; asm("mov.b64 {%0,%1},%2;" : "=f"(f.x), "=f"(f.y) : "l"(v)); return f;
}
#define FMA2(d,a,b,c) asm("fma.rn.f32x2 %0,%1,%2,%3;" : "=l"(d) : "l"(a), "l"(b), "l"(c))
#define ADD2(d,a,b)   asm("add.rn.f32x2 %0,%1,%2;"    : "=l"(d) : "l"(a), "l"(b))
#define MUL2(d,a,b)   asm("mul.rn.f32x2 %0,%1,%2;"    : "=l"(d) : "l"(a), "l"(b))

__device__ __forceinline__ u64 relu2(u64 v) {
    float2 f = up(v);
    return pk(fmaxf(f.x, 0.f), fmaxf(f.y, 0.f));
}

// ---------------------------------------------------------------------------
// Kernel 1a: per-(t,n) column stats over b (ddof=1). 4 threads per column,
// each sums 32 b values; coalesced 128B warp loads; smem combine.
// grid = 32 blocks x 512 threads. Stats written in [n][t] layout.
// ---------------------------------------------------------------------------
__global__ void __launch_bounds__(512) stats_kernel(const float* __restrict__ x) {
    __shared__ float ss[4][128], sq[4][128];
    int q  = threadIdx.x >> 7;            // 0..3 (b sub-range)
    int cl = threadIdx.x & 127;
    int gc = blockIdx.x * 128 + cl;       // global column = t*16+n

    float s = 0.f, qq = 0.f;
#pragma unroll 8
    for (int b = q * 32; b < q * 32 + 32; b++) {
        float v = x[b * 4096 + gc];
        s += v; qq = fmaf(v, v, qq);
    }
    ss[q][cl] = s; sq[q][cl] = qq;
    __syncthreads();
    if (threadIdx.x < 128) {
        float S = ss[0][cl] + ss[1][cl] + ss[2][cl] + ss[3][cl];
        float Q = sq[0][cl] + sq[1][cl] + sq[2][cl] + sq[3][cl];
        float mu = S * (1.f / 128.f);
        float ri = 1.f / sqrtf((Q - S * mu) * (1.f / 127.f));
        int t = gc >> 4, n = gc & 15;
        g_mu[n * Tt + t] = mu;
        g_ri[n * Tt + t] = ri;
    }
}

// ---------------------------------------------------------------------------
// Kernel 1b: transpose + normalize: x[b][t][n] -> g_xs[n][b*256+t].
// 8b x 32t x 16n smem tile; coalesced loads and 64B-contiguous stores.
// grid = (16 b-chunks, 8 t-chunks), 256 threads.
// ---------------------------------------------------------------------------
__global__ void __launch_bounds__(256) transpose_kernel(const float* __restrict__ x) {
    __shared__ float tile[8][16][33];   // [b][n][t]
    int b0 = blockIdx.x * 8;
    int t0 = blockIdx.y * 32;
    int tid = threadIdx.x;

#pragma unroll
    for (int r = 0; r < 4; r++) {
        int f  = r * 256 + tid;
        int n4 = f & 3;
        int tl = (f >> 2) & 31;
        int bl = f >> 7;
        float4 v = *(const float4*)(x + ((size_t)((b0 + bl) * Tt + t0 + tl)) * Nn + n4 * 4);
        tile[bl][n4 * 4 + 0][tl] = v.x;
        tile[bl][n4 * 4 + 1][tl] = v.y;
        tile[bl][n4 * 4 + 2][tl] = v.z;
        tile[bl][n4 * 4 + 3][tl] = v.w;
    }
    __syncthreads();

    int half = tid & 1;
    int pair = tid >> 1;       // 0..127
    int bl = pair & 7;
    int n  = pair >> 3;

    const float* pm = g_mu + n * Tt + t0 + half * 16;
    const float* pr = g_ri + n * Tt + t0 + half * 16;
    float* outp = g_xs + n * BT + (b0 + bl) * Tt + t0 + half * 16;

#pragma unroll
    for (int r = 0; r < 4; r++) {
        float4 m  = *(const float4*)(pm + r * 4);
        float4 ir = *(const float4*)(pr + r * 4);
        int tl = half * 16 + r * 4;
        float4 o;
        o.x = (tile[bl][n][tl + 0] - m.x) * ir.x;
        o.y = (tile[bl][n][tl + 1] - m.y) * ir.y;
        o.z = (tile[bl][n][tl + 2] - m.z) * ir.z;
        o.w = (tile[bl][n][tl + 3] - m.w) * ir.w;
        *(float4*)(outp + r * 4) = o;
    }
}

// ---------------------------------------------------------------------------
// Kernel 2: MLP sweep, packed f32x2, 8 samples per thread (4 packed pairs).
// LN1 applied in-register once; layer-2 accumulators initialized with b2;
// LN2 folded into the head via streamed stats. Block = 128. grid = (K*N, 32).
// ---------------------------------------------------------------------------
__global__ void __launch_bounds__(128) mlp_kernel(
    const float* __restrict__ W1, const float* __restrict__ b1,
    const float* __restrict__ W2, const float* __restrict__ b2,
    const float* __restrict__ W3, const float* __restrict__ b3)
{
    __shared__ __align__(16) float sw2f[Hh][Hh * 2];   // [o][2i..2i+1] = dup W2[o][i]
    __shared__ __align__(16) float sw1b1[Hh][4];       // {w1,w1,b1,b1}
    __shared__ __align__(16) float sb2w3[Hh][4];       // {b2,b2,w3,w3}
    __shared__ __align__(16) float sc[4];              // {w3sum,w3sum,b3,b3}

    int kn = blockIdx.x;          // k*N + n
    int n  = kn & 15;
    int k  = kn >> 4;
    int tid = threadIdx.x;

    for (int idx = tid; idx < Hh * Hh; idx += 128) {
        float v = W2[kn * Hh * Hh + idx];
        int o = idx / Hh, i = idx % Hh;
        sw2f[o][2 * i] = v; sw2f[o][2 * i + 1] = v;
    }
    if (tid < Hh) {
        float w = W1[kn * Hh + tid], b = b1[kn * Hh + tid];
        sw1b1[tid][0] = w; sw1b1[tid][1] = w;
        sw1b1[tid][2] = b; sw1b1[tid][3] = b;
        float bb = b2[kn * Hh + tid];
        float w3 = W3[kn * Hh + tid];
        sb2w3[tid][0] = bb; sb2w3[tid][1] = bb;
        sb2w3[tid][2] = w3; sb2w3[tid][3] = w3;
    }
    if (tid == 0) {
        float s3 = 0.f;
#pragma unroll
        for (int i = 0; i < Hh; i++) s3 += W3[kn * Hh + i];
        sc[0] = s3; sc[1] = s3;
        float bb3 = b3[kn];
        sc[2] = bb3; sc[3] = bb3;
    }
    __syncthreads();

    const float* xs = g_xs + n * BT;
    float* tout = g_t + (size_t)(k * Nn + n) * BT;

    int j0 = (blockIdx.y * 128 + tid) * 8;
    float4 xa = *(const float4*)(xs + j0);
    float4 xb = *(const float4*)(xs + j0 + 4);
    u64 xp[4];
    xp[0] = pk(xa.x, xa.y); xp[1] = pk(xa.z, xa.w);
    xp[2] = pk(xb.x, xb.y); xp[3] = pk(xb.z, xb.w);

    const u64 ZERO = 0ull;
    const u64 c005  = pk(0.05f, 0.05f);
    const u64 cn005 = pk(-0.05f, -0.05f);

    // ---- layer 1 with streamed LN1 stats ----
    u64 h[4][Hh];
    u64 s1[4], q1[4];
#pragma unroll
    for (int p = 0; p < 4; p++) { s1[p] = ZERO; q1[p] = ZERO; }
#pragma unroll
    for (int i = 0; i < Hh; i++) {
        ulonglong2 wb = *(const ulonglong2*)&sw1b1[i][0];
#pragma unroll
        for (int p = 0; p < 4; p++) {
            u64 t; FMA2(t, xp[p], wb.x, wb.y);
            t = relu2(t);
            h[p][i] = t;
            ADD2(s1[p], s1[p], t);
            FMA2(q1[p], t, t, q1[p]);
        }
    }
    // LN1: normalize h in place (one FMA each: h*r + (-mu*r))
#pragma unroll
    for (int p = 0; p < 4; p++) {
        u64 mu, nmu, ex, var;
        MUL2(mu,  s1[p], c005);
        MUL2(nmu, s1[p], cn005);
        MUL2(ex,  q1[p], c005);
        FMA2(var, mu, nmu, ex);     // E[h^2] - mu^2 (biased)
        float2 vf = up(var);
        float rx = rsqrtf(vf.x + 1e-5f);
        float ry = rsqrtf(vf.y + 1e-5f);
        u64 r1 = pk(rx, ry);
        u64 v1; MUL2(v1, nmu, r1);  // -mu*r
#pragma unroll
        for (int i = 0; i < Hh; i++)
            FMA2(h[p][i], h[p][i], r1, v1);
    }

    // ---- layer 2 matmul; accumulators start at b2; stream LN2 stats + W3 dot ----
    u64 s2[4], q2[4], d3[4];
#pragma unroll
    for (int p = 0; p < 4; p++) { s2[p] = ZERO; q2[p] = ZERO; d3[p] = ZERO; }

#pragma unroll 2
    for (int o = 0; o < Hh; o++) {
        const ulonglong2* wrow = (const ulonglong2*)&sw2f[o][0];
        ulonglong2 bw = *(const ulonglong2*)&sb2w3[o][0];   // {b2 dup, w3 dup}
        u64 a[4];
        a[0] = bw.x; a[1] = bw.x; a[2] = bw.x; a[3] = bw.x;
#pragma unroll
        for (int q = 0; q < Hh / 2; q++) {
            ulonglong2 wv = wrow[q];
#pragma unroll
            for (int p = 0; p < 4; p++) {
                FMA2(a[p], h[p][2 * q],     wv.x, a[p]);
                FMA2(a[p], h[p][2 * q + 1], wv.y, a[p]);
            }
        }
#pragma unroll
        for (int p = 0; p < 4; p++) {
            u64 h2 = relu2(a[p]);
            ADD2(s2[p], s2[p], h2);
            FMA2(q2[p], h2, h2, q2[p]);
            FMA2(d3[p], h2, bw.y, d3[p]);
        }
    }

    // ---- LN2 fold + head ----
    u64 w3s = *(const u64*)&sc[0];
    u64 b3d = *(const u64*)&sc[2];
    float outv[8];
#pragma unroll
    for (int p = 0; p < 4; p++) {
        u64 mu2, nmu2, ex2, var2;
        MUL2(mu2,  s2[p], c005);
        MUL2(nmu2, s2[p], cn005);
        MUL2(ex2,  q2[p], c005);
        FMA2(var2, mu2, nmu2, ex2);
        float2 vf = up(var2);
        float rx = rsqrtf(vf.x + 1e-5f);
        float ry = rsqrtf(vf.y + 1e-5f);
        u64 r2 = pk(rx, ry);
        u64 tmp; FMA2(tmp, nmu2, w3s, d3[p]);
        u64 o2;  FMA2(o2, r2, tmp, b3d);
        float2 of = up(o2);
        outv[2 * p] = of.x; outv[2 * p + 1] = of.y;
    }
    *(float4*)(tout + j0)     = make_float4(outv[0], outv[1], outv[2], outv[3]);
    *(float4*)(tout + j0 + 4) = make_float4(outv[4], outv[5], outv[6], outv[7]);
}

// ---------------------------------------------------------------------------
// Kernel 3: penalty. prod_marginals underflows to exactly 0 in fp32 (product
// of 16 values each ~1e-7), so d = -prod_joint and we only need per-n stats
// plus one product pass. 2 smem passes total.
// grid = K*T/4 = 640 blocks, 128 threads (4 warps; warp = one tq).
// ---------------------------------------------------------------------------
#define PB 4

__global__ void __launch_bounds__(128) penalty_kernel(float* __restrict__ out) {
    int bid = blockIdx.x;            // 0..639
    int k   = bid >> 6;
    int tt0 = (bid & 63) * PB;

    __shared__ float s[64][132];     // [n*4+tq][b]
    __shared__ float sac[64][2];     // per col: {r, -mu*r}
    __shared__ float part[4];
    __shared__ unsigned int s_last;

    int tid = threadIdx.x;
    int b = tid;

    // load: per n, one float4 (4 consecutive t), sector-aligned
#pragma unroll
    for (int n = 0; n < 16; n++) {
        float4 v = *(const float4*)(g_t + ((size_t)(k * 16 + n)) * BT + b * 256 + tt0);
        s[n * 4 + 0][b] = v.x;
        s[n * 4 + 1][b] = v.y;
        s[n * 4 + 2][b] = v.z;
        s[n * 4 + 3][b] = v.w;
    }
    __syncthreads();

    // fused stats pass: sum + sumsq over b (2 threads per column)
    int col = tid >> 1, hf = tid & 1;
    float S = 0.f, Q = 0.f;
#pragma unroll 8
    for (int i = 0; i < 64; i++) {
        float v = s[col][hf * 64 + i];
        S += v; Q = fmaf(v, v, Q);
    }
    S += __shfl_xor_sync(0xffffffffu, S, 1);
    Q += __shfl_xor_sync(0xffffffffu, Q, 1);
    if (hf == 0) {
        float mu = S * (1.f / 128.f);
        float r  = 1.f / (sqrtf((Q - S * mu) * (1.f / 127.f)) + 1e-8f);
        sac[col][0] = r;
        sac[col][1] = -mu * r;
    }
    __syncthreads();

    // product pass: warp = tq; coefficients in registers (broadcast LDS)
    int tq = tid >> 5, lane = tid & 31;
    float2 ac[16];
#pragma unroll
    for (int n = 0; n < 16; n++)
        ac[n] = *(const float2*)&sac[n * 4 + tq][0];

    float acc = 0.f;
#pragma unroll
    for (int j = 0; j < 4; j++) {
        int bb = lane + 32 * j;               // stride-1 across lanes: conflict-free
        float prod = fmaf(s[0 * 4 + tq][bb], ac[0].x, ac[0].y);
#pragma unroll
        for (int n = 1; n < 16; n++)
            prod *= fmaf(s[n * 4 + tq][bb], ac[n].x, ac[n].y);
        acc += prod;
    }
#pragma unroll
    for (int o = 16; o; o >>= 1) acc += __shfl_xor_sync(0xffffffffu, acc, o);
    if (lane == 0) {
        float pj = acc * (1.f / 128.f);       // d = 0 - pj; d^2 = pj^2
        g_sq[k * Tt + tt0 + tq] = pj * pj;
    }

    // completion counter: last block reduces g_sq deterministically
    __threadfence();
    __syncthreads();
    if (tid == 0) {
        unsigned int t = atomicAdd(&g_ctr, 1u);
        s_last = (t == (unsigned int)(Kk * Tt / PB - 1)) ? 1u : 0u;
    }
    __syncthreads();
    if (s_last) {
        __threadfence();
        float facc = 0.f;
        for (int i = tid; i < KT; i += 128) facc += g_sq[i];
#pragma unroll
        for (int o = 16; o; o >>= 1) facc += __shfl_xor_sync(0xffffffffu, facc, o);
        if ((tid & 31) == 0) part[tid >> 5] = facc;
        __syncthreads();
        if (tid == 0) {
            out[0] = (part[0] + part[1] + part[2] + part[3]) * (1.f / (float)KT);
            g_ctr = 0u;   // reset for next graph replay
        }
    }
}

// ---------------------------------------------------------------------------
extern "C" void kernel_launch(void* const* d_in, const int* in_sizes, int n_in,
                              void* d_out, int out_size) {
    const float* x  = (const float*)d_in[0];
    const float* W1 = (const float*)d_in[1];
    const float* b1 = (const float*)d_in[2];
    const float* W2 = (const float*)d_in[3];
    const float* b2 = (const float*)d_in[4];
    const float* W3 = (const float*)d_in[5];
    const float* b3 = (const float*)d_in[6];

    stats_kernel<<<32, 512>>>(x);

    dim3 g1(16, 8);
    transpose_kernel<<<g1, 256>>>(x);

    dim3 g2(Kk * Nn, 32);
    mlp_kernel<<<g2, 128>>>(W1, b1, W2, b2, W3, b3);

    penalty_kernel<<<KT / PB, 128>>>((float*)d_out);
}